// round 1
// baseline (speedup 1.0000x reference)
#include <cuda_runtime.h>
#include <cuda_bf16.h>
#include <math.h>

#define NN     200000
#define EE     3200000
#define GG     256
#define HID    128
#define NLAYER 3
#define EPSV   1e-5f

#define NCHUNK 1024
#define CHUNK  196              // ceil(NN/NCHUNK)
#define BM     64               // gemm rows per block
#define APITCH 132              // padded A-tile pitch (floats), 132*4 % 16 == 0
#define GEMM_SMEM ((BM*APITCH + HID*HID) * 4)

// ---------------- scratch (device globals; no allocation allowed) ----------------
__device__ float g_bufA[(size_t)NN * HID];
__device__ float g_bufB[(size_t)NN * HID];
__device__ int   g_rowptr[NN + 1];
__device__ int   g_cursor[NN];
__device__ int   g_cols[EE];
__device__ float g_vals[EE];
__device__ int   g_chunk[NCHUNK];
__device__ float g_sum[GG * HID];
__device__ float g_sumsq[GG * HID];
__device__ float g_scale[GG * HID];
__device__ float g_shift[GG * HID];
__device__ int   g_cnt[GG];

// ---------------- node embedding + input projection: h0 = embed(x) @ W_in + b_in ----------------
__global__ void embed_kernel(const float* __restrict__ x,
                             const float* __restrict__ Win,
                             const float* __restrict__ bin,
                             float* __restrict__ out) {
    __shared__ float Ws[15 * HID];
    __shared__ float bs[HID];
    int tid = threadIdx.x; // blockDim = 128
    for (int i = tid; i < 15 * HID; i += 128) Ws[i] = Win[i];
    bs[tid] = bin[tid];
    __syncthreads();
    const float dts[4] = {1.0f, 0.1f, 0.01f, 0.001f}; // exp(-2k*ln(1e4)/8)
    for (int n = blockIdx.x; n < NN; n += gridDim.x) {
        float t  = x[n * 3 + 0];
        float ar = x[n * 3 + 1];
        float ap = x[n * 3 + 2];
        int ti = min(max(__float2int_rz(t), 0), 5);
        float la = log1pf(ar);
        float acc = bs[tid] + Ws[ti * HID + tid] + la * Ws[6 * HID + tid];
        #pragma unroll
        for (int k = 0; k < 4; k++) {
            float sv, cv;
            sincosf(ap * dts[k], &sv, &cv);
            acc += sv * Ws[(7 + 2 * k) * HID + tid] + cv * Ws[(8 + 2 * k) * HID + tid];
        }
        out[(size_t)n * HID + tid] = acc;
    }
}

// ---------------- per-graph node counts ----------------
__global__ void hist_batch(const int* __restrict__ batch) {
    __shared__ int h[GG];
    for (int i = threadIdx.x; i < GG; i += blockDim.x) h[i] = 0;
    __syncthreads();
    for (int i = blockIdx.x * blockDim.x + threadIdx.x; i < NN; i += gridDim.x * blockDim.x)
        atomicAdd(&h[batch[i]], 1);
    __syncthreads();
    for (int i = threadIdx.x; i < GG; i += blockDim.x)
        if (h[i]) atomicAdd(&g_cnt[i], h[i]);
}

// ---------------- CSR build: histogram -> scan -> scatter ----------------
__global__ void hist_rows(const int* __restrict__ er) {
    int i = blockIdx.x * blockDim.x + threadIdx.x;
    if (i < EE) atomicAdd(&g_cursor[er[i]], 1);
}

__global__ void scan_chunks() {
    int t = blockIdx.x * blockDim.x + threadIdx.x;
    if (t >= NCHUNK) return;
    int base = t * CHUNK;
    int lim = min(base + CHUNK, NN);
    int s = 0;
    for (int i = base; i < lim; i++) s += g_cursor[i];
    g_chunk[t] = s;
}

__global__ void scan_excl() {
    __shared__ int s[NCHUNK];
    int t = threadIdx.x;
    int v = g_chunk[t];
    s[t] = v;
    __syncthreads();
    for (int off = 1; off < NCHUNK; off <<= 1) {
        int add = (t >= off) ? s[t - off] : 0;
        __syncthreads();
        s[t] += add;
        __syncthreads();
    }
    g_chunk[t] = s[t] - v; // exclusive
}

__global__ void scan_write() {
    int t = blockIdx.x * blockDim.x + threadIdx.x;
    if (t >= NCHUNK) return;
    if (t == 0) g_rowptr[NN] = EE;
    int base = t * CHUNK;
    int lim = min(base + CHUNK, NN);
    int run = g_chunk[t];
    for (int i = base; i < lim; i++) {
        int c = g_cursor[i];
        g_rowptr[i] = run;
        g_cursor[i] = run;
        run += c;
    }
}

__global__ void scatter_edges(const int* __restrict__ er,
                              const int* __restrict__ ec,
                              const float* __restrict__ ev) {
    int i = blockIdx.x * blockDim.x + threadIdx.x;
    if (i < EE) {
        int p = atomicAdd(&g_cursor[er[i]], 1);
        g_cols[p] = ec[i];
        g_vals[p] = ev[i];
    }
}

// ---------------- SpMM (CSR, warp per row, float4 per lane) ----------------
__global__ void spmm_csr(const float* __restrict__ H, float* __restrict__ out) {
    int w = (blockIdx.x * blockDim.x + threadIdx.x) >> 5;
    int lane = threadIdx.x & 31;
    if (w >= NN) return;
    int beg = g_rowptr[w];
    int end = g_rowptr[w + 1];
    int c4 = lane * 4;
    float4 acc = make_float4(0.f, 0.f, 0.f, 0.f);
    for (int e = beg; e < end; e++) {
        int c = __ldg(&g_cols[e]);
        float v = __ldg(&g_vals[e]);
        float4 hv = *(const float4*)&H[(size_t)c * HID + c4];
        acc.x = fmaf(v, hv.x, acc.x);
        acc.y = fmaf(v, hv.y, acc.y);
        acc.z = fmaf(v, hv.z, acc.z);
        acc.w = fmaf(v, hv.w, acc.w);
    }
    *(float4*)&out[(size_t)w * HID + c4] = acc;
}

// ---------------- GEMM (y = A @ W + b) fused with per-graph sum / sumsq stats ----------------
__global__ __launch_bounds__(256, 2)
void gemm_stats(const float* __restrict__ A, const float* __restrict__ W,
                const float* __restrict__ bias, const int* __restrict__ batch,
                float* __restrict__ Y) {
    extern __shared__ float sm[];
    float* Asm = sm;                 // [BM][APITCH]
    float* Wsm = sm + BM * APITCH;   // [HID][HID]
    int tid = threadIdx.x;
    int row0 = blockIdx.x * BM;

    // load W tile (128x128)
    const float4* Wg = (const float4*)W;
    float4* Wd = (float4*)Wsm;
    #pragma unroll
    for (int i = 0; i < 16; i++) Wd[tid + i * 256] = Wg[tid + i * 256];
    // load A tile (64x128) with padded pitch
    for (int i = tid; i < BM * 32; i += 256) {
        int r = i >> 5, k4 = (i & 31) << 2;
        *(float4*)&Asm[r * APITCH + k4] = *(const float4*)&A[(size_t)(row0 + r) * HID + k4];
    }
    __syncthreads();

    int tx = tid & 15, ty = tid >> 4;
    int cb = tx * 8, rb = ty * 4;
    float acc[4][8];
    #pragma unroll
    for (int r = 0; r < 4; r++)
        #pragma unroll
        for (int j = 0; j < 8; j++) acc[r][j] = 0.f;

    #pragma unroll 4
    for (int k = 0; k < HID; k++) {
        float a[4];
        #pragma unroll
        for (int r = 0; r < 4; r++) a[r] = Asm[(rb + r) * APITCH + k];
        float4 w0 = *(float4*)&Wsm[k * HID + cb];
        float4 w1 = *(float4*)&Wsm[k * HID + cb + 4];
        float wv[8] = {w0.x, w0.y, w0.z, w0.w, w1.x, w1.y, w1.z, w1.w};
        #pragma unroll
        for (int r = 0; r < 4; r++)
            #pragma unroll
            for (int j = 0; j < 8; j++)
                acc[r][j] = fmaf(a[r], wv[j], acc[r][j]);
    }

    float bv[8];
    #pragma unroll
    for (int j = 0; j < 8; j++) bv[j] = bias[cb + j];

    float s[8], q[8];
    #pragma unroll
    for (int j = 0; j < 8; j++) { s[j] = 0.f; q[j] = 0.f; }

    #pragma unroll
    for (int r = 0; r < 4; r++) {
        float y[8];
        #pragma unroll
        for (int j = 0; j < 8; j++) {
            y[j] = acc[r][j] + bv[j];
            s[j] += y[j];
            q[j] += y[j] * y[j];
        }
        size_t off = (size_t)(row0 + rb + r) * HID + cb;
        *(float4*)&Y[off]     = make_float4(y[0], y[1], y[2], y[3]);
        *(float4*)&Y[off + 4] = make_float4(y[4], y[5], y[6], y[7]);
    }

    int gfirst = batch[row0];
    int glast  = batch[row0 + BM - 1];
    if (gfirst == glast) {
        // fast path: whole block is one graph -> tree-reduce over ty, 1 atomic per col
        float* red = Asm; // reuse
        __syncthreads();
        *(float4*)&red[ty * APITCH + cb]     = make_float4(s[0], s[1], s[2], s[3]);
        *(float4*)&red[ty * APITCH + cb + 4] = make_float4(s[4], s[5], s[6], s[7]);
        __syncthreads();
        #pragma unroll
        for (int st = 8; st >= 1; st >>= 1) {
            if (ty < st) {
                #pragma unroll
                for (int j = 0; j < 8; j++)
                    red[ty * APITCH + cb + j] += red[(ty + st) * APITCH + cb + j];
            }
            __syncthreads();
        }
        if (ty == 0) {
            #pragma unroll
            for (int j = 0; j < 8; j++)
                atomicAdd(&g_sum[gfirst * HID + cb + j], red[cb + j]);
        }
        __syncthreads();
        *(float4*)&red[ty * APITCH + cb]     = make_float4(q[0], q[1], q[2], q[3]);
        *(float4*)&red[ty * APITCH + cb + 4] = make_float4(q[4], q[5], q[6], q[7]);
        __syncthreads();
        #pragma unroll
        for (int st = 8; st >= 1; st >>= 1) {
            if (ty < st) {
                #pragma unroll
                for (int j = 0; j < 8; j++)
                    red[ty * APITCH + cb + j] += red[(ty + st) * APITCH + cb + j];
            }
            __syncthreads();
        }
        if (ty == 0) {
            #pragma unroll
            for (int j = 0; j < 8; j++)
                atomicAdd(&g_sumsq[gfirst * HID + cb + j], red[cb + j]);
        }
    } else {
        // slow path: graph boundary inside block (rare; ~8% of blocks)
        #pragma unroll
        for (int r = 0; r < 4; r++) {
            int g = batch[row0 + rb + r];
            #pragma unroll
            for (int j = 0; j < 8; j++) {
                float y = acc[r][j] + bv[j];
                atomicAdd(&g_sum[g * HID + cb + j], y);
                atomicAdd(&g_sumsq[g * HID + cb + j], y * y);
            }
        }
    }
}

// ---------------- GraphNorm stat finalize:  var(y - a*m) = E[y^2] - a(2-a)m^2 ----------------
__global__ void finalize_stats(const float* __restrict__ alphas,
                               const float* __restrict__ gammas,
                               const float* __restrict__ betas, int l) {
    int i = blockIdx.x * blockDim.x + threadIdx.x;
    if (i >= GG * HID) return;
    int g = i >> 7, c = i & 127;
    float cnt = fmaxf((float)g_cnt[g], 1.f);
    float m  = g_sum[i] / cnt;
    float e2 = g_sumsq[i] / cnt;
    float al = alphas[l];
    float var = e2 - al * (2.f - al) * m * m;
    float rstd = rsqrtf(fmaxf(var, 0.f) + EPSV);
    float ga = gammas[l * HID + c];
    g_scale[i] = rstd * ga;
    g_shift[i] = betas[l * HID + c] - al * m * rstd * ga;
}

// ---------------- normalize (+ optional relu) ----------------
__global__ void norm_kernel(const float* __restrict__ Y, const int* __restrict__ batch,
                            float* __restrict__ out, int relu) {
    int idx = blockIdx.x * blockDim.x + threadIdx.x; // NN*32 threads, float4 each
    if (idx >= NN * 32) return;
    int n = idx >> 5, c4 = (idx & 31) * 4;
    int g = batch[n];
    float4 y  = *(const float4*)&Y[(size_t)n * HID + c4];
    float4 sc = *(const float4*)&g_scale[g * HID + c4];
    float4 sh = *(const float4*)&g_shift[g * HID + c4];
    float4 r;
    r.x = fmaf(y.x, sc.x, sh.x);
    r.y = fmaf(y.y, sc.y, sh.y);
    r.z = fmaf(y.z, sc.z, sh.z);
    r.w = fmaf(y.w, sc.w, sh.w);
    if (relu) {
        r.x = fmaxf(r.x, 0.f); r.y = fmaxf(r.y, 0.f);
        r.z = fmaxf(r.z, 0.f); r.w = fmaxf(r.w, 0.f);
    }
    *(float4*)&out[(size_t)n * HID + c4] = r;
}

// ---------------- launch ----------------
extern "C" void kernel_launch(void* const* d_in, const int* in_sizes, int n_in,
                              void* d_out, int out_size) {
    const float* x      = (const float*)d_in[0];
    const int*   er     = (const int*)d_in[1];
    const int*   ec     = (const int*)d_in[2];
    const float* ev     = (const float*)d_in[3];
    const int*   batch  = (const int*)d_in[4];
    const float* Win    = (const float*)d_in[5];
    const float* bin    = (const float*)d_in[6];
    const float* Ws     = (const float*)d_in[7];
    const float* bs     = (const float*)d_in[8];
    const float* alphas = (const float*)d_in[9];
    const float* gammas = (const float*)d_in[10];
    const float* betas  = (const float*)d_in[11];
    float* out = (float*)d_out;

    cudaFuncSetAttribute(gemm_stats, cudaFuncAttributeMaxDynamicSharedMemorySize, GEMM_SMEM);

    float *A, *B;
    void *pcnt, *pcur, *psum, *psq;
    cudaGetSymbolAddress((void**)&A, g_bufA);
    cudaGetSymbolAddress((void**)&B, g_bufB);
    cudaGetSymbolAddress(&pcnt, g_cnt);
    cudaGetSymbolAddress(&pcur, g_cursor);
    cudaGetSymbolAddress(&psum, g_sum);
    cudaGetSymbolAddress(&psq,  g_sumsq);

    cudaMemsetAsync(pcnt, 0, GG * sizeof(int), 0);
    cudaMemsetAsync(pcur, 0, NN * sizeof(int), 0);

    embed_kernel<<<2048, 128>>>(x, Win, bin, A);
    hist_batch<<<256, 256>>>(batch);

    hist_rows<<<EE / 256, 256>>>(er);
    scan_chunks<<<4, 256>>>();
    scan_excl<<<1, NCHUNK>>>();
    scan_write<<<4, 256>>>();
    scatter_edges<<<EE / 256, 256>>>(er, ec, ev);

    for (int l = 0; l < NLAYER; l++) {
        const float* in = (l & 1) ? B : A;
        float* agg = (l & 1) ? A : B;
        float* y = (float*)in;                       // overwrite input buffer with y
        float* hout = (l == NLAYER - 1) ? out : agg; // last layer writes d_out

        spmm_csr<<<NN / 8, 256>>>(in, agg);
        cudaMemsetAsync(psum, 0, GG * HID * sizeof(float), 0);
        cudaMemsetAsync(psq,  0, GG * HID * sizeof(float), 0);
        gemm_stats<<<NN / BM, 256, GEMM_SMEM>>>(agg, Ws + (size_t)l * HID * HID,
                                                bs + l * HID, batch, y);
        finalize_stats<<<(GG * HID) / 256, 256>>>(alphas, gammas, betas, l);
        norm_kernel<<<(NN * 32) / 256, 256>>>(y, batch, hout, (l < NLAYER - 1) ? 1 : 0);
    }
}